// round 5
// baseline (speedup 1.0000x reference)
#include <cuda_runtime.h>
#include <cuda_bf16.h>
#include <math.h>

// ---------------------------------------------------------------------------
// WarpNet on GB300 — Round 5: convs as implicit GEMM on classic mma.sync
// (HMMA bf16, compiles at compute_103; tcgen05 is rejected by the harness
// toolchain). 3-term bf16 emulation: D ~= Ahi*Bhi + Alo*Bhi + Ahi*Blo.
// Per CTA: M=128 co x N=128 px (2 rows) x K=4608 in 144 chunks of 32.
// A (weights) pre-shuffled in gmem to per-thread fragment order (no smem).
// B built per tap into 8x8-block smem layout (conflict-free ldmatrix).
// ---------------------------------------------------------------------------

#define NIMG   4
#define CIN    512
#define HW     64
#define C1     256
#define C2     128
#define NCLS   124
#define NPAIR  2
#define KTOT   4608
#define X_ELEMS (2 * NCLS * HW * HW)
#define NCHUNK 144            // 16 ci-blocks x 9 taps

typedef unsigned int u32;

// ---------------- scratch (device globals; no allocations allowed) ----------
__device__ float g_sbuf [NIMG * C1 * HW * HW];
__device__ float g_y2   [NPAIR * HW * HW];
__device__ float g_wgt  [25 * NPAIR * HW * HW];
__device__ float g_final[NPAIR * HW * HW * C1];
__device__ float g_WT   [256 * NCLS];
__device__ __align__(16) u32 g_Xpk[NIMG * CIN * HW * HW];   // bf16 hi|lo packed
__device__ __align__(16) u32 g_A1hi[C1 * KTOT / 2];         // frag-ordered weights
__device__ __align__(16) u32 g_A1lo[C1 * KTOT / 2];
__device__ __align__(16) u32 g_A2hi[C2 * KTOT / 2];
__device__ __align__(16) u32 g_A2lo[C2 * KTOT / 2];

// ---------------- helpers ----------------------------------------------------
__device__ __forceinline__ u32 smem_u32(const void* p) {
    u32 a;
    asm("{ .reg .u64 t; cvta.to.shared.u64 t, %1; cvt.u32.u64 %0, t; }"
        : "=r"(a) : "l"(p));
    return a;
}
__device__ __forceinline__ void ldmx2(u32& r0, u32& r1, u32 addr) {
    asm volatile("ldmatrix.sync.aligned.m8n8.x2.shared.b16 {%0,%1}, [%2];"
        : "=r"(r0), "=r"(r1) : "r"(addr));
}
__device__ __forceinline__ void mma_bf16(float* d, const u32* a, const u32* b) {
    asm volatile("mma.sync.aligned.m16n8k16.row.col.f32.bf16.bf16.f32 "
        "{%0,%1,%2,%3}, {%4,%5,%6,%7}, {%8,%9}, {%0,%1,%2,%3};"
        : "+f"(d[0]), "+f"(d[1]), "+f"(d[2]), "+f"(d[3])
        : "r"(a[0]), "r"(a[1]), "r"(a[2]), "r"(a[3]), "r"(b[0]), "r"(b[1]));
}

// dynamic smem: staging [32ci][4row][66col] u32, then B tiles
#define STG_U32  (32 * 4 * 66)          // 8448 u32 = 33792 B
#define OFF_B    (STG_U32 * 4)          // byte offset of B tiles
#define B_TILE   8192                    // one 128x32 bf16 tile
// B tiles: [buf(2)][hi/lo][8192 B]
#define SMEM_SZ  (OFF_B + 4 * B_TILE)   // 66560 B

// ---------------- prep kernels ------------------------------------------------
__global__ void prep_x(const float* __restrict__ x)
{
    int i = blockIdx.x * 256 + threadIdx.x;
    float v = x[i];
    __nv_bfloat16 h = __float2bfloat16(v);
    __nv_bfloat16 l = __float2bfloat16(v - __bfloat162float(h));
    g_Xpk[i] = (u32)__bfloat16_as_ushort(h) | ((u32)__bfloat16_as_ushort(l) << 16);
}

// Weights -> per-thread fragment order.
// dst u32 i: lane=i&31, q=(i>>5)&15, wm=(i>>9)&3, blk=i>>11; blk = cz*144 + c;
// kb=q>>3, f=(q>>2)&1, reg=q&3;
// co = cz*128 + wm*32 + f*16 + (lane>>2) + (reg&1)*8
// k  = kb*16 + 2*(lane&3) + (reg>>1)*8  (two bf16: k, k+1)
// c -> cib=c/9, p=c%9; ci = cib*32 + k; src = W[(co*512 + ci)*9 + p]
__global__ void prep_w(const float* __restrict__ W, u32* __restrict__ Ahi,
                       u32* __restrict__ Alo)
{
    int i = blockIdx.x * 256 + threadIdx.x;
    int lane = i & 31, q = (i >> 5) & 15, wm = (i >> 9) & 3, blk = i >> 11;
    int cz = blk / NCHUNK, c = blk - cz * NCHUNK;
    int kb = q >> 3, f = (q >> 2) & 1, reg = q & 3;
    int co = cz * 128 + wm * 32 + f * 16 + (lane >> 2) + (reg & 1) * 8;
    int k  = kb * 16 + 2 * (lane & 3) + (reg >> 1) * 8;
    int cib = c / 9, p = c - cib * 9;
    int ci = cib * 32 + k;
    float v0 = W[((size_t)co * 512 + ci    ) * 9 + p];
    float v1 = W[((size_t)co * 512 + ci + 1) * 9 + p];
    __nv_bfloat16 h0 = __float2bfloat16(v0);
    __nv_bfloat16 h1 = __float2bfloat16(v1);
    __nv_bfloat16 l0 = __float2bfloat16(v0 - __bfloat162float(h0));
    __nv_bfloat16 l1 = __float2bfloat16(v1 - __bfloat162float(h1));
    Ahi[i] = (u32)__bfloat16_as_ushort(h0) | ((u32)__bfloat16_as_ushort(h1) << 16);
    Alo[i] = (u32)__bfloat16_as_ushort(l0) | ((u32)__bfloat16_as_ushort(l1) << 16);
}

// ---------------- conv via mma.sync -------------------------------------------
template<int COUT, bool TO_SBUF>
__global__ __launch_bounds__(256, 1)
void conv_mma(const u32* __restrict__ Ahi, const u32* __restrict__ Alo,
              const float* __restrict__ bg, const float* __restrict__ bb,
              const float* __restrict__ bm, const float* __restrict__ bv,
              float* __restrict__ out_ext)
{
    extern __shared__ char smem[];
    u32* stg = (u32*)smem;
    const u32 sb = smem_u32(smem);

    const int t   = threadIdx.x;
    const int l   = t & 31;
    const int wid = t >> 5;
    const int wm  = wid & 3;
    const int wn  = wid >> 2;
    const int h0  = blockIdx.x * 2;
    const int cz  = blockIdx.y;
    const int img = blockIdx.z;

    float acc[2][8][4];
    #pragma unroll
    for (int f = 0; f < 2; ++f)
        #pragma unroll
        for (int nf = 0; nf < 8; ++nf)
            #pragma unroll
            for (int r = 0; r < 4; ++r) acc[f][nf][r] = 0.f;

    const u32* Xpk = g_Xpk + (size_t)img * CIN * HW * HW;
    const u32* Abh = Ahi + (size_t)cz * NCHUNK * 2048 + wm * 512 + l;
    const u32* Abl = Alo + (size_t)cz * NCHUNK * 2048 + wm * 512 + l;

    // B build per-thread constants: n = t>>1, k-half = (t&1)*16
    const int bn = t >> 1, ks = (t & 1) * 16;
    const int br = bn >> 6, bw = bn & 63;
    // ldmatrix per-lane base (within a buffer's hi tile)
    const u32 lm_base = sb + OFF_B + (u32)(wn * 4096 + ((l >> 3) & 1) * 128 + (l & 7) * 16);
    // store base within hi tile
    const u32 st_base = sb + OFF_B + (u32)(((bn >> 3) * 4 + (ks >> 3)) * 128 + (bn & 7) * 16);

    int chunk = 0;
    for (int cib = 0; cib < 16; ++cib) {
        __syncthreads();   // staging WAR vs previous chunk's B build reads
        for (int e = t; e < STG_U32; e += 256) {
            int ci  = e / 264;
            int rem = e - ci * 264;
            int row = rem / 66;
            int col = rem - row * 66;
            int gh  = h0 + row - 1;
            int gw  = col - 1;
            u32 v = 0;
            if ((unsigned)gh < 64u && (unsigned)gw < 64u)
                v = Xpk[((size_t)(cib * 32 + ci) * HW + gh) * HW + gw];
            stg[e] = v;
        }
        __syncthreads();

        for (int p = 0; p < 9; ++p, ++chunk) {
            const int buf = chunk & 1;
            // ---- build B (hi, lo) tiles for this tap ----
            {
                const u32* src = stg + (br + p / 3) * 66 + (bw + p % 3);
                u32 hb = st_base + (u32)(buf * 16384);
                #pragma unroll
                for (int j = 0; j < 8; ++j) {
                    u32 v0 = src[(ks + 2 * j    ) * 264];
                    u32 v1 = src[(ks + 2 * j + 1) * 264];
                    u32 hw2 = (v0 & 0xFFFFu) | (v1 << 16);
                    u32 lw2 = (v0 >> 16) | (v1 & 0xFFFF0000u);
                    u32 off = (u32)(((2 * j) >> 3) * 128 + ((2 * j) & 7) * 2);
                    asm volatile("st.shared.b32 [%0], %1;" :: "r"(hb + off), "r"(hw2) : "memory");
                    asm volatile("st.shared.b32 [%0], %1;" :: "r"(hb + off + B_TILE), "r"(lw2) : "memory");
                }
            }
            // ---- A fragment loads (coalesced LDG.32, overlap the barrier) ----
            u32 ah[16], al[16];
            {
                const u32* aph = Abh + (size_t)chunk * 2048;
                const u32* apl = Abl + (size_t)chunk * 2048;
                #pragma unroll
                for (int q = 0; q < 16; ++q) { ah[q] = aph[q * 32]; al[q] = apl[q * 32]; }
            }
            __syncthreads();

            const u32 lb = lm_base + (u32)(buf * 16384);
            #pragma unroll
            for (int kb = 0; kb < 2; ++kb) {
                u32 bh[8][2], bl_[8][2];
                #pragma unroll
                for (int nf = 0; nf < 8; ++nf) {
                    u32 a = lb + (u32)(nf * 512 + kb * 256);
                    ldmx2(bh[nf][0],  bh[nf][1],  a);
                    ldmx2(bl_[nf][0], bl_[nf][1], a + B_TILE);
                }
                #pragma unroll
                for (int f = 0; f < 2; ++f) {
                    const u32* a_h = ah + kb * 8 + f * 4;
                    const u32* a_l = al + kb * 8 + f * 4;
                    #pragma unroll
                    for (int nf = 0; nf < 8; ++nf) {
                        mma_bf16(acc[f][nf], a_h, bh[nf]);
                        mma_bf16(acc[f][nf], a_l, bh[nf]);
                        mma_bf16(acc[f][nf], a_h, bl_[nf]);
                    }
                }
            }
        }
    }

    // ---- epilogue: BN + ReLU, write NCHW ----
    float* op = TO_SBUF ? g_sbuf : out_ext;
    #pragma unroll
    for (int f = 0; f < 2; ++f) {
        int co0 = cz * 128 + wm * 32 + f * 16 + (l >> 2);
        float sc0 = bg[co0] * rsqrtf(bv[co0] + 1e-5f);
        float bi0 = bb[co0] - bm[co0] * sc0;
        float sc1 = bg[co0 + 8] * rsqrtf(bv[co0 + 8] + 1e-5f);
        float bi1 = bb[co0 + 8] - bm[co0 + 8] * sc1;
        #pragma unroll
        for (int nf = 0; nf < 8; ++nf) {
            int n0 = wn * 64 + nf * 8 + 2 * (l & 3);
            int row = h0 + (n0 >> 6), w = n0 & 63;
            float v0 = fmaf(acc[f][nf][0], sc0, bi0);
            float v1 = fmaf(acc[f][nf][1], sc0, bi0);
            float v2 = fmaf(acc[f][nf][2], sc1, bi1);
            float v3 = fmaf(acc[f][nf][3], sc1, bi1);
            *(float2*)(op + (((size_t)img * COUT + co0    ) * HW + row) * HW + w) =
                make_float2(v0 > 0.f ? v0 : 0.f, v1 > 0.f ? v1 : 0.f);
            *(float2*)(op + (((size_t)img * COUT + co0 + 8) * HW + row) * HW + w) =
                make_float2(v2 > 0.f ? v2 : 0.f, v3 > 0.f ? v3 : 0.f);
        }
    }
}

// ---------------------------------------------------------------------------
__global__ void y2_kernel(const float* __restrict__ ce2)
{
    int nb = blockIdx.x;
    int n = nb >> 6, h = nb & 63, w = threadIdx.x;
    const float* p = ce2 + ((size_t)n * C2 * HW + h) * HW + w;
    float acc = 0.f;
    for (int c = 0; c < C2; ++c) {
        float v = p[(size_t)c * HW * HW];
        acc = fmaf(v, v, acc);
    }
    g_y2[(n * HW + h) * HW + w] = acc;
}

// ---------------------------------------------------------------------------
__global__ __launch_bounds__(512)
void wgt_kernel(const float* __restrict__ ce2)
{
    __shared__ float s_oth[8][5][68];
    __shared__ float s_acc[26][4][64];

    int nb = blockIdx.x;
    int n = nb >> 6, h = nb & 63;
    int t = threadIdx.x;
    int cg = t >> 6, w = t & 63;

    float acc[25];
    #pragma unroll
    for (int o = 0; o < 25; ++o) acc[o] = 0.f;
    float x2 = 0.f;

    const float* oth = ce2 + (size_t)n       * C2 * HW * HW;
    const float* c2  = ce2 + (size_t)(2 + n) * C2 * HW * HW;

    for (int c0 = 0; c0 < C2; c0 += 8) {
        __syncthreads();
        for (int e = t; e < 2720; e += 512) {
            int ec  = e / 340;
            int rem = e - ec * 340;
            int rr  = rem / 68;
            int ww  = rem - rr * 68;
            int gh  = h + rr - 2;
            int gw  = ww - 2;
            float v = 0.f;
            if ((unsigned)gh < 64u && (unsigned)gw < 64u)
                v = oth[((size_t)(c0 + ec) * HW + gh) * HW + gw];
            s_oth[ec][rr][ww] = v;
        }
        __syncthreads();

        float cv = c2[((size_t)(c0 + cg) * HW + h) * HW + w];
        x2 = fmaf(cv, cv, x2);
        #pragma unroll
        for (int o = 0; o < 25; ++o)
            acc[o] = fmaf(cv, s_oth[cg][o / 5][w + (o % 5)], acc[o]);
    }

    __syncthreads();
    if (cg >= 4) {
        #pragma unroll
        for (int o = 0; o < 25; ++o) s_acc[o][cg - 4][w] = acc[o];
        s_acc[25][cg - 4][w] = x2;
    }
    __syncthreads();
    if (cg < 4) {
        #pragma unroll
        for (int o = 0; o < 25; ++o) s_acc[o][cg][w] += acc[o];
        s_acc[25][cg][w] += x2;
    }
    __syncthreads();

    if (cg == 0) {
        float X2 = s_acc[25][0][w] + s_acc[25][1][w] + s_acc[25][2][w] + s_acc[25][3][w];
        float inv[25];
        #pragma unroll
        for (int o = 0; o < 25; ++o) {
            float cr = s_acc[o][0][w] + s_acc[o][1][w] + s_acc[o][2][w] + s_acc[o][3][w];
            int gh = h + (o / 5) - 2;
            int gw = w + (o % 5) - 2;
            float y2v = 1e20f;
            if ((unsigned)gh < 64u && (unsigned)gw < 64u)
                y2v = g_y2[(n * HW + gh) * HW + gw];
            float dist = X2 + y2v - 2.f * cr;
            inv[o] = 1.f / (dist + 1e-5f);
        }
        float m = inv[0];
        #pragma unroll
        for (int o = 1; o < 25; ++o) m = fmaxf(m, inv[o]);
        float s = 0.f;
        #pragma unroll
        for (int o = 0; o < 25; ++o) { inv[o] = expf(inv[o] - m); s += inv[o]; }
        float rs = 1.f / s;
        #pragma unroll
        for (int o = 0; o < 25; ++o)
            g_wgt[((o * NPAIR + n) * HW + h) * HW + w] = inv[o] * rs;
    }
}

// ---------------------------------------------------------------------------
__global__ __launch_bounds__(256)
void warp_kernel()
{
    __shared__ float s_w25[25][64];
    __shared__ float s_oth[4][5][68];

    int nb = blockIdx.x;
    int n = nb >> 6, h = nb & 63;
    int t = threadIdx.x;

    for (int e = t; e < 1600; e += 256) {
        int o = e >> 6, ww = e & 63;
        s_w25[o][ww] = g_wgt[((o * NPAIR + n) * HW + h) * HW + ww];
    }

    const float* oth = g_sbuf + (size_t)n       * C1 * HW * HW;
    const float* cim = g_sbuf + (size_t)(2 + n) * C1 * HW * HW;
    int cc = t >> 6, w = t & 63;

    for (int c0 = 0; c0 < C1; c0 += 4) {
        __syncthreads();
        for (int e = t; e < 1360; e += 256) {
            int ec  = e / 340;
            int rem = e - ec * 340;
            int rr  = rem / 68;
            int ww  = rem - rr * 68;
            int gh  = h + rr - 2;
            int gw  = ww - 2;
            float v = 0.f;
            if ((unsigned)gh < 64u && (unsigned)gw < 64u)
                v = oth[((size_t)(c0 + ec) * HW + gh) * HW + gw];
            s_oth[ec][rr][ww] = v;
        }
        __syncthreads();

        float civ = cim[((size_t)(c0 + cc) * HW + h) * HW + w];
        float a = 0.f;
        #pragma unroll
        for (int o = 0; o < 25; ++o)
            a = fmaf(s_w25[o][w], s_oth[cc][o / 5][w + (o % 5)], a);
        float res = 0.5f * (civ + a * (1.0f / 25.0f));
        g_final[(((size_t)n * HW + h) * HW + w) * C1 + c0 + cc] = res;
    }
}

// ---------------------------------------------------------------------------
__global__ void wt_kernel(const float* __restrict__ lw)
{
    int o = blockIdx.x, c = threadIdx.x;
    g_WT[c * NCLS + o] = lw[o * 256 + c];
}

// ---------------------------------------------------------------------------
__global__ __launch_bounds__(128)
void head_kernel(const float* __restrict__ lb, float* __restrict__ xout)
{
    __shared__ float s_x[8][256];
    __shared__ float s_red[128];

    int pg = blockIdx.x;
    int t  = threadIdx.x;

    for (int e = t; e < 2048; e += 128) {
        int pp = e >> 8, c = e & 255;
        s_x[pp][c] = g_final[((size_t)pg * 8 + pp) * 256 + c];
    }
    __syncthreads();

    float acc[8];
    #pragma unroll
    for (int pp = 0; pp < 8; ++pp) acc[pp] = 0.f;

    if (t < NCLS) {
        for (int c = 0; c < 256; ++c) {
            float wv = g_WT[c * NCLS + t];
            #pragma unroll
            for (int pp = 0; pp < 8; ++pp)
                acc[pp] = fmaf(s_x[pp][c], wv, acc[pp]);
        }
        float bias = lb[t];
        #pragma unroll
        for (int pp = 0; pp < 8; ++pp) acc[pp] += bias;
    }

    for (int pp = 0; pp < 8; ++pp) {
        __syncthreads();
        s_red[t] = (t < NCLS) ? acc[pp] : -3.4e38f;
        __syncthreads();
        for (int s = 64; s > 0; s >>= 1) {
            if (t < s) s_red[t] = fmaxf(s_red[t], s_red[t + s]);
            __syncthreads();
        }
        float mx = s_red[0];
        __syncthreads();
        s_red[t] = (t < NCLS) ? expf(acc[pp] - mx) : 0.f;
        __syncthreads();
        for (int s = 64; s > 0; s >>= 1) {
            if (t < s) s_red[t] += s_red[t + s];
            __syncthreads();
        }
        float lse = mx + logf(s_red[0]);

        int pix = pg * 8 + pp;
        int n = pix >> 12, h = (pix >> 6) & 63, w = pix & 63;
        if (t < NCLS)
            xout[(((size_t)n * NCLS + t) * HW + h) * HW + w] = acc[pp] - lse;
    }
}

// ---------------------------------------------------------------------------
extern "C" void kernel_launch(void* const* d_in, const int* in_sizes, int n_in,
                              void* d_out, int out_size)
{
    const float* clip  = (const float*)d_in[0];
    const float* embW  = (const float*)d_in[2];
    const float* eg    = (const float*)d_in[3];
    const float* eb    = (const float*)d_in[4];
    const float* em    = (const float*)d_in[5];
    const float* ev    = (const float*)d_in[6];
    const float* emb2W = (const float*)d_in[7];
    const float* e2g   = (const float*)d_in[8];
    const float* e2b   = (const float*)d_in[9];
    const float* e2m   = (const float*)d_in[10];
    const float* e2v   = (const float*)d_in[11];
    const float* lastW = (const float*)d_in[12];
    const float* lastb = (const float*)d_in[13];

    float* xout = (float*)d_out;
    float* ce2  = (float*)d_out + X_ELEMS;

    cudaFuncSetAttribute(conv_mma<C2, false>,
        cudaFuncAttributeMaxDynamicSharedMemorySize, SMEM_SZ);
    cudaFuncSetAttribute(conv_mma<C1, true>,
        cudaFuncAttributeMaxDynamicSharedMemorySize, SMEM_SZ);

    prep_x<<<NIMG * CIN * HW * HW / 256, 256>>>(clip);
    prep_w<<<C1 * KTOT / 2 / 256, 256>>>(embW,  g_A1hi, g_A1lo);
    prep_w<<<C2 * KTOT / 2 / 256, 256>>>(emb2W, g_A2hi, g_A2lo);

    conv_mma<C2, false><<<dim3(32, 1, NIMG), 256, SMEM_SZ>>>(
        g_A2hi, g_A2lo, e2g, e2b, e2m, e2v, ce2);
    conv_mma<C1, true><<<dim3(32, 2, NIMG), 256, SMEM_SZ>>>(
        g_A1hi, g_A1lo, eg, eb, em, ev, nullptr);

    y2_kernel <<<NPAIR * HW, 64>>>(ce2);
    wgt_kernel<<<NPAIR * HW, 512>>>(ce2);
    warp_kernel<<<NPAIR * HW, 256>>>();
    wt_kernel  <<<NCLS, 256>>>(lastW);
    head_kernel<<<(NPAIR * HW * HW) / 8, 128>>>(lastb, xout);
}